// round 6
// baseline (speedup 1.0000x reference)
#include <cuda_runtime.h>
#include <cstdint>

#define T_STEPS 800
#define UNITS   1024
#define BATCH   32
#define NFEAT   161
#define GRID    128
#define TPR     128
#define CLIPV   20.0f

// 128 CTAs = 16 clusters (k-chunks) x 8 ranks (col-tiles)
#define CK 16
#define CN 8
#define KC 64            // UNITS / CK
#define NC 128           // UNITS / CN

#define SMEM_U_BYTES (KC * NC * 4)            // 32768 U tile
#define SMEM_H_BYTES (2 * 2 * KC * BATCH * 4) // 32768 h chunk, double buf x 2 dir
#define SMEM_BYTES   (SMEM_U_BYTES + SMEM_H_BYTES)

__device__ float    g_xw[T_STEPS * UNITS * BATCH];   // [t][u][b]
__device__ float    g_part[3][2][CK][UNITS][BATCH];  // triple-buffered partials
__device__ unsigned g_P[CN];                         // producer counters (16/round)
__device__ unsigned g_X;                             // xw-phase barrier

typedef unsigned long long ull;

__device__ __forceinline__ void fma2(ull& d, ull a, ull b) {
    asm("fma.rn.f32x2 %0, %1, %2, %0;" : "+l"(d) : "l"(a), "l"(b));
}
__device__ __forceinline__ ull pack2(float v) {
    ull r; asm("mov.b64 %0, {%1, %1};" : "=l"(r) : "f"(v)); return r;
}
__device__ __forceinline__ float2 unpack2(ull v) {
    float2 r; asm("mov.b64 {%0, %1}, %2;" : "=f"(r.x), "=f"(r.y) : "l"(v)); return r;
}

__device__ __forceinline__ void ctr_arrive(unsigned* c) {
    __syncthreads();
    if (threadIdx.x == 0)
        asm volatile("red.release.gpu.global.add.u32 [%0], %1;"
                     :: "l"(c), "r"(1u) : "memory");
}
__device__ __forceinline__ void ctr_wait(unsigned* c, unsigned target) {
    if (threadIdx.x == 0) {
        unsigned v;
        do {
            asm volatile("ld.acquire.gpu.global.u32 %0, [%1];"
                         : "=r"(v) : "l"(c) : "memory");
        } while (v < target);
    }
    __syncthreads();
}

__device__ __forceinline__ uint32_t smem_u32(const void* p) {
    uint32_t a;
    asm("{ .reg .u64 t; cvta.to.shared.u64 t, %1; cvt.u32.u64 %0, t; }"
        : "=r"(a) : "l"(p));
    return a;
}
__device__ __forceinline__ void st_cluster_v4(uint32_t laddr, int rank, float4 v) {
    uint32_t remote;
    asm volatile("mapa.shared::cluster.u32 %0, %1, %2;"
                 : "=r"(remote) : "r"(laddr), "r"(rank));
    asm volatile("st.shared::cluster.v4.f32 [%0], {%1, %2, %3, %4};"
                 :: "r"(remote), "f"(v.x), "f"(v.y), "f"(v.z), "f"(v.w) : "memory");
}
__device__ __forceinline__ void cluster_sync() {
    asm volatile("barrier.cluster.arrive.aligned;" ::: "memory");
    asm volatile("barrier.cluster.wait.aligned;" ::: "memory");
}

// ---------------------------------------------------------------------------
__global__ void init_kernel() {
    int i = blockIdx.x * blockDim.x + threadIdx.x;
    if (i < CN) g_P[i] = 0u;
    if (i == CN) g_X = 0u;
}

// ---------------------------------------------------------------------------
// Persistent kernel: xw phase -> global barrier -> bidirectional scan.
// ---------------------------------------------------------------------------
__global__ void __launch_bounds__(TPR, 1) __cluster_dims__(CN, 1, 1)
main_kernel(const float* __restrict__ inp,  const float* __restrict__ W,
            const float* __restrict__ Uw,   const float* __restrict__ bias,
            float* __restrict__ out) {
    extern __shared__ __align__(16) char smem_raw[];
    float* U_s = reinterpret_cast<float*>(smem_raw);                   // [64][128]
    float* h_s = reinterpret_cast<float*>(smem_raw + SMEM_U_BYTES);    // [2][2][64][32]
    float* in_s = h_s;                                                 // xw-phase overlay

    const int tid = threadIdx.x;
    const int bid = blockIdx.x;
    const int kc  = bid >> 3;            // cluster id
    const int nc  = bid & 7;             // cluster rank
    const int k0  = kc * KC;
    const int c0  = nc * NC;

    const int b0 = (tid & 7) * 4;        // 8 batch groups of 4
    const int cc = (tid >> 3) * 8;       // 16 col groups of 8

    // reduce identity: (dir, local unit, batch-quad)
    const int rdir = tid >> 6;
    const int lu   = nc * 8 + ((tid >> 3) & 7);   // local unit within chunk
    const int ru   = k0 + lu;                     // global unit
    const int rb4  = tid & 7;

    const uint32_t h_u32 = smem_u32(h_s);

    // ================= xw phase =================
    // xw[t][u][b] = sum_f inp[b][t][f] * W[f][u] + bias[u]
    // 6400 tasks (t, utile of 128 units), 50 per CTA.
    for (int i = 0; i < 50; i++) {
        int tau = bid * 50 + i;
        int t   = tau >> 3;
        int u0  = (tau & 7) * 128;
        __syncthreads();
        for (int idx = tid; idx < BATCH * NFEAT; idx += TPR) {
            int b = idx / NFEAT;
            int f = idx - b * NFEAT;
            in_s[f * 36 + b] = inp[(b * T_STEPS + t) * NFEAT + f];
        }
        __syncthreads();

        const int uu = u0 + (tid >> 3) * 8;   // 8 units per thread
        ull acc[8][2];
        #pragma unroll
        for (int j = 0; j < 8; j++) { acc[j][0] = 0ull; acc[j][1] = 0ull; }

        const float4* Wp = reinterpret_cast<const float4*>(W) + (uu >> 2);
        #pragma unroll 1
        for (int f = 0; f < NFEAT; f++) {
            ulonglong2 ip = *reinterpret_cast<const ulonglong2*>(&in_s[f * 36 + b0]);
            float4 wA = __ldg(Wp + f * (UNITS / 4));
            float4 wB = __ldg(Wp + f * (UNITS / 4) + 1);
            ull s0 = pack2(wA.x), s1 = pack2(wA.y), s2 = pack2(wA.z), s3 = pack2(wA.w);
            ull s4 = pack2(wB.x), s5 = pack2(wB.y), s6 = pack2(wB.z), s7 = pack2(wB.w);
            fma2(acc[0][0], ip.x, s0); fma2(acc[0][1], ip.y, s0);
            fma2(acc[1][0], ip.x, s1); fma2(acc[1][1], ip.y, s1);
            fma2(acc[2][0], ip.x, s2); fma2(acc[2][1], ip.y, s2);
            fma2(acc[3][0], ip.x, s3); fma2(acc[3][1], ip.y, s3);
            fma2(acc[4][0], ip.x, s4); fma2(acc[4][1], ip.y, s4);
            fma2(acc[5][0], ip.x, s5); fma2(acc[5][1], ip.y, s5);
            fma2(acc[6][0], ip.x, s6); fma2(acc[6][1], ip.y, s6);
            fma2(acc[7][0], ip.x, s7); fma2(acc[7][1], ip.y, s7);
        }
        #pragma unroll
        for (int j = 0; j < 8; j++) {
            float bu = __ldg(bias + uu + j);
            float2 a0 = unpack2(acc[j][0]);
            float2 a1 = unpack2(acc[j][1]);
            __stcg(reinterpret_cast<float4*>(&g_xw[((t * UNITS) + uu + j) * BATCH + b0]),
                   make_float4(a0.x + bu, a0.y + bu, a1.x + bu, a1.y + bu));
        }
    }
    ctr_arrive(&g_X);
    ctr_wait(&g_X, GRID);

    // ================= scan prologue =================
    // U tile (natural fp32, 32 KB)
    for (int idx = tid; idx < KC * NC / 4; idx += TPR) {
        reinterpret_cast<float4*>(U_s)[idx] =
            __ldg(reinterpret_cast<const float4*>(Uw + k0 * UNITS + c0
                      + (idx >> 5) * UNITS) + (idx & 31));
    }
    // zero h buf 0 (h_{-1} = 0)
    for (int idx = tid; idx < 2 * KC * BATCH; idx += TPR) h_s[idx] = 0.0f;
    __syncthreads();

    int rbuf = 0;   // buffer holding h_{t-1}
    int pb   = 0;   // partial buffer = t % 3

    for (int t = 0; t < T_STEPS; t++) {
        // prefetch x for this round's reduce
        int xt = rdir ? (T_STEPS - 1 - t) : t;
        float4 xv = __ldcg(reinterpret_cast<const float4*>(
                        g_xw + (xt * UNITS + ru) * BATCH) + rb4);

        // ---- fused GEMM (both dirs), acc[dir][bpair][col] ----
        ull acc[2][2][8];
        #pragma unroll
        for (int d = 0; d < 2; d++)
            #pragma unroll
            for (int p = 0; p < 2; p++)
                #pragma unroll
                for (int i = 0; i < 8; i++) acc[d][p][i] = 0ull;
        {
            const float* hp = h_s + rbuf * (2 * KC * BATCH) + b0;
            const float* up = U_s + cc;
            #pragma unroll 8
            for (int k = 0; k < KC; k++) {
                ulonglong2 hA = *reinterpret_cast<const ulonglong2*>(hp + k * BATCH);
                ulonglong2 hB = *reinterpret_cast<const ulonglong2*>(hp + KC * BATCH + k * BATCH);
                float4 uA = *reinterpret_cast<const float4*>(up + k * NC);
                float4 uB = *reinterpret_cast<const float4*>(up + k * NC + 4);
                ull s0 = pack2(uA.x), s1 = pack2(uA.y), s2 = pack2(uA.z), s3 = pack2(uA.w);
                ull s4 = pack2(uB.x), s5 = pack2(uB.y), s6 = pack2(uB.z), s7 = pack2(uB.w);
                fma2(acc[0][0][0], hA.x, s0); fma2(acc[0][1][0], hA.y, s0);
                fma2(acc[0][0][1], hA.x, s1); fma2(acc[0][1][1], hA.y, s1);
                fma2(acc[0][0][2], hA.x, s2); fma2(acc[0][1][2], hA.y, s2);
                fma2(acc[0][0][3], hA.x, s3); fma2(acc[0][1][3], hA.y, s3);
                fma2(acc[0][0][4], hA.x, s4); fma2(acc[0][1][4], hA.y, s4);
                fma2(acc[0][0][5], hA.x, s5); fma2(acc[0][1][5], hA.y, s5);
                fma2(acc[0][0][6], hA.x, s6); fma2(acc[0][1][6], hA.y, s6);
                fma2(acc[0][0][7], hA.x, s7); fma2(acc[0][1][7], hA.y, s7);
                fma2(acc[1][0][0], hB.x, s0); fma2(acc[1][1][0], hB.y, s0);
                fma2(acc[1][0][1], hB.x, s1); fma2(acc[1][1][1], hB.y, s1);
                fma2(acc[1][0][2], hB.x, s2); fma2(acc[1][1][2], hB.y, s2);
                fma2(acc[1][0][3], hB.x, s3); fma2(acc[1][1][3], hB.y, s3);
                fma2(acc[1][0][4], hB.x, s4); fma2(acc[1][1][4], hB.y, s4);
                fma2(acc[1][0][5], hB.x, s5); fma2(acc[1][1][5], hB.y, s5);
                fma2(acc[1][0][6], hB.x, s6); fma2(acc[1][1][6], hB.y, s6);
                fma2(acc[1][0][7], hB.x, s7); fma2(acc[1][1][7], hB.y, s7);
            }
        }

        // ---- store partials ----
        #pragma unroll
        for (int d = 0; d < 2; d++)
            #pragma unroll
            for (int i = 0; i < 8; i++) {
                float2 a0 = unpack2(acc[d][0][i]);
                float2 a1 = unpack2(acc[d][1][i]);
                __stcg(reinterpret_cast<float4*>(
                           &g_part[pb][d][kc][c0 + cc + i][b0]),
                       make_float4(a0.x, a0.y, a1.x, a1.y));
            }
        ctr_arrive(&g_P[nc]);

        // ---- wait for the 16 producers of our h-chunk's partials ----
        ctr_wait(&g_P[kc >> 1], 16u * (t + 1));

        // ---- reduce own slice (8 units x 32 b x 2 dir per CTA) ----
        float4 hn;
        {
            const float4* base = reinterpret_cast<const float4*>(
                                     &g_part[pb][rdir][0][ru][0]) + rb4;
            float4 s = __ldcg(base);
            #pragma unroll
            for (int j = 1; j < CK; j++) {
                float4 p = __ldcg(base + j * (UNITS * BATCH / 4));
                s.x += p.x; s.y += p.y; s.z += p.z; s.w += p.w;
            }
            hn.x = fminf(fmaxf(xv.x + s.x, 0.f), CLIPV);
            hn.y = fminf(fmaxf(xv.y + s.y, 0.f), CLIPV);
            hn.z = fminf(fmaxf(xv.z + s.z, 0.f), CLIPV);
            hn.w = fminf(fmaxf(xv.w + s.w, 0.f), CLIPV);
        }

        // ---- scatter slice into all 8 cluster peers' h_s (buf rbuf^1) ----
        {
            uint32_t dst = h_u32
                + ((((rbuf ^ 1) * 2 + rdir) * KC + lu) * BATCH + rb4 * 4) * 4;
            #pragma unroll
            for (int r = 0; r < CN; r++) st_cluster_v4(dst, r, hn);
        }
        cluster_sync();

        rbuf ^= 1;
        pb = pb + 1; if (pb == 3) pb = 0;
    }

    // epilogue: h_799 in buf 0; rank-0 CTA of each cluster writes its chunk
    if (nc == 0) {
        #pragma unroll
        for (int i = 0; i < 16; i++) {
            int idx = tid + i * TPR;            // 2048 = 32 b x 64 k
            int b = idx >> 6, k = idx & 63;
            out[b * UNITS + k0 + k] = h_s[k * BATCH + b] +
                                      h_s[KC * BATCH + k * BATCH + b];
        }
    }
}

// ---------------------------------------------------------------------------
extern "C" void kernel_launch(void* const* d_in, const int* in_sizes, int n_in,
                              void* d_out, int out_size) {
    const float* inp  = (const float*)d_in[0];  // [32, 800, 161]
    const float* W    = (const float*)d_in[1];  // [161, 1024]
    const float* Uw   = (const float*)d_in[2];  // [1024, 1024]
    const float* bias = (const float*)d_in[3];  // [1024]
    float* out        = (float*)d_out;          // [32, 1024]

    cudaFuncSetAttribute(main_kernel, cudaFuncAttributeMaxDynamicSharedMemorySize,
                         SMEM_BYTES);

    init_kernel<<<1, 32>>>();
    main_kernel<<<GRID, TPR, SMEM_BYTES>>>(inp, W, Uw, bias, out);
}

// round 8
// speedup vs baseline: 1.1295x; 1.1295x over previous
#include <cuda_runtime.h>
#include <cstdint>

#define T_STEPS 800
#define UNITS   1024
#define BATCH   32
#define NFEAT   161
#define GRID    128
#define TPB     256     // xw/init kernels
#define TPR     128     // rnn kernel
#define CLIPV   20.0f

// 128 CTAs = 16 k-chunks x 8 col-tiles
#define CK 16
#define CN 8
#define KC 64            // UNITS / CK
#define NC 128           // UNITS / CN

#define SMEM_U_BYTES (KC * NC * 4)        // 32768: U tile
#define SMEM_H_BYTES (2 * KC * BATCH * 4) // 16384: h chunk, both dirs
#define SMEM_BYTES   (SMEM_U_BYTES + SMEM_H_BYTES)

#define QNAN_U 0x7fc00000u

__device__ float g_xw[T_STEPS * UNITS * BATCH];        // [t][u][b]
__device__ float g_part[3][2][CK][UNITS][BATCH];       // partials, NaN-sentinel
__device__ float g_hrep[3][CK][CN][2][KC][BATCH];      // per-consumer h replicas

typedef unsigned long long ull;

__device__ __forceinline__ void fma2(ull& d, ull a, ull b) {
    asm("fma.rn.f32x2 %0, %1, %2, %0;" : "+l"(d) : "l"(a), "l"(b));
}
__device__ __forceinline__ ull pack2(float v) {
    ull r; asm("mov.b64 %0, {%1, %1};" : "=l"(r) : "f"(v)); return r;
}
__device__ __forceinline__ float2 unpack2(ull v) {
    float2 r; asm("mov.b64 {%0, %1}, %2;" : "=f"(r.x), "=f"(r.y) : "l"(v)); return r;
}

// Volatile-ish L2 load for polling (re-executes every call; bypasses L1).
__device__ __forceinline__ float4 ld_poll(const float4* p) {
    float4 v;
    asm volatile("ld.global.cg.v4.f32 {%0,%1,%2,%3}, [%4];"
                 : "=f"(v.x), "=f"(v.y), "=f"(v.z), "=f"(v.w)
                 : "l"(p) : "memory");
    return v;
}
// NaN check robust to fast-math: integer compare (sentinel = qNaN).
// Real payloads are always finite (h clipped to [0,20], weights small).
__device__ __forceinline__ bool nan4(float4 v) {
    unsigned a = (__float_as_uint(v.x) & 0x7fffffffu) > 0x7f800000u;
    unsigned b = (__float_as_uint(v.y) & 0x7fffffffu) > 0x7f800000u;
    unsigned c = (__float_as_uint(v.z) & 0x7fffffffu) > 0x7f800000u;
    unsigned d = (__float_as_uint(v.w) & 0x7fffffffu) > 0x7f800000u;
    return (a | b | c | d) != 0u;
}
__device__ __forceinline__ void fence_argp() {
    asm volatile("fence.acq_rel.gpu;" ::: "memory");
}

// ---------------------------------------------------------------------------
// init: NaN-fill both exchange arenas (every harness call; globals persist)
// ---------------------------------------------------------------------------
#define N_PART_F (3 * 2 * CK * UNITS * BATCH)
#define N_HREP_F (3 * CK * CN * 2 * KC * BATCH)
__global__ void init_kernel() {
    const float qn = __uint_as_float(QNAN_U);
    int stride = gridDim.x * blockDim.x;
    for (int i = blockIdx.x * blockDim.x + threadIdx.x; i < N_PART_F; i += stride)
        ((float*)g_part)[i] = qn;
    for (int i = blockIdx.x * blockDim.x + threadIdx.x; i < N_HREP_F; i += stride)
        ((float*)g_hrep)[i] = qn;
}

// ---------------------------------------------------------------------------
// xw[t][u][b] = sum_f inputs[b][t][f] * W[f][u] + bias[u]
// ---------------------------------------------------------------------------
__global__ void __launch_bounds__(TPB) xw_kernel(const float* __restrict__ inp,
                                                 const float* __restrict__ W,
                                                 const float* __restrict__ bias) {
    __shared__ __align__(16) float in_s[NFEAT * 36];
    const int t   = blockIdx.y;
    const int u0  = blockIdx.x * 128;
    const int tid = threadIdx.x;
    const int bq  = tid & 7;
    const int cq  = tid >> 3;

    for (int idx = tid; idx < BATCH * NFEAT; idx += TPB) {
        int b = idx / NFEAT;
        int f = idx - b * NFEAT;
        in_s[f * 36 + b] = inp[(b * T_STEPS + t) * NFEAT + f];
    }
    __syncthreads();

    ull acc[4][2];
    #pragma unroll
    for (int i = 0; i < 4; i++) { acc[i][0] = 0ull; acc[i][1] = 0ull; }

    const float4* Wp = reinterpret_cast<const float4*>(W) + (u0 >> 2) + cq;
    #pragma unroll 1
    for (int f = 0; f < NFEAT; f++) {
        ulonglong2 ip = *reinterpret_cast<const ulonglong2*>(&in_s[f * 36 + bq * 4]);
        float4 w4 = __ldg(Wp + f * (UNITS / 4));
        ull w0 = pack2(w4.x), w1 = pack2(w4.y), w2 = pack2(w4.z), w3 = pack2(w4.w);
        fma2(acc[0][0], ip.x, w0); fma2(acc[0][1], ip.y, w0);
        fma2(acc[1][0], ip.x, w1); fma2(acc[1][1], ip.y, w1);
        fma2(acc[2][0], ip.x, w2); fma2(acc[2][1], ip.y, w2);
        fma2(acc[3][0], ip.x, w3); fma2(acc[3][1], ip.y, w3);
    }
    #pragma unroll
    for (int i = 0; i < 4; i++) {
        int u = u0 + cq * 4 + i;
        float bu = __ldg(bias + u);
        float2 a0 = unpack2(acc[i][0]);
        float2 a1 = unpack2(acc[i][1]);
        float4 v = make_float4(a0.x + bu, a0.y + bu, a1.x + bu, a1.y + bu);
        *reinterpret_cast<float4*>(&g_xw[(t * UNITS + u) * BATCH + bq * 4]) = v;
    }
}

// ---------------------------------------------------------------------------
// Persistent bidirectional scan — counter-free NaN-sentinel dataflow.
// CTA (kc,nc): produces partials (h-chunk kc x col-tile nc, both dirs),
// reduces slice = units [64kc+8nc, +8) x 2 dirs, publishes to 8 private
// replicas, and stages its chunk by polling its own replica.
// ---------------------------------------------------------------------------
__global__ void __launch_bounds__(TPR, 1) rnn_kernel(const float* __restrict__ Uw,
                                                     float* __restrict__ out) {
    extern __shared__ __align__(16) char smem_raw[];
    float* U_s = reinterpret_cast<float*>(smem_raw);                  // [64][128]
    float* h_s = reinterpret_cast<float*>(smem_raw + SMEM_U_BYTES);   // [2][64][32]

    const int tid = threadIdx.x;
    const int bid = blockIdx.x;
    const int kc  = bid >> 3;
    const int nc  = bid & 7;
    const int k0  = kc * KC;
    const int c0  = nc * NC;

    const int b0 = (tid & 7) * 4;        // 8 batch groups of 4
    const int cc = (tid >> 3) * 8;       // 16 col groups of 8

    // reduce identity: (dir, local unit in slice, batch-quad)
    const int rdir = tid >> 6;
    const int lu   = (tid >> 3) & 7;
    const int ru   = k0 + nc * 8 + lu;   // global unit
    const int rb4  = tid & 7;

    const float4 qn4 = make_float4(__uint_as_float(QNAN_U), __uint_as_float(QNAN_U),
                                   __uint_as_float(QNAN_U), __uint_as_float(QNAN_U));

    // ---- load U tile once (32 KB) ----
    for (int idx = tid; idx < KC * NC / 4; idx += TPR) {
        reinterpret_cast<float4*>(U_s)[idx] =
            __ldg(reinterpret_cast<const float4*>(Uw + k0 * UNITS + c0
                      + (idx >> 5) * UNITS) + (idx & 31));
    }
    // ---- h_{-1} = 0 ----
    for (int idx = tid; idx < 2 * KC * BATCH; idx += TPR) h_s[idx] = 0.0f;
    __syncthreads();

    int pb = 0;                          // buffer index = t % 3
    float4 hn;                           // this thread's reduced slice piece

    for (int t = 0; t < T_STEPS; t++) {
        // ---- fused GEMM (both dirs), acc[dir][bpair][col] ----
        ull acc[2][2][8];
        #pragma unroll
        for (int d = 0; d < 2; d++)
            #pragma unroll
            for (int p = 0; p < 2; p++)
                #pragma unroll
                for (int i = 0; i < 8; i++) acc[d][p][i] = 0ull;
        {
            const float* hp = h_s + b0;
            const float* up = U_s + cc;
            #pragma unroll 8
            for (int k = 0; k < KC; k++) {
                ulonglong2 hA = *reinterpret_cast<const ulonglong2*>(hp + k * BATCH);
                ulonglong2 hB = *reinterpret_cast<const ulonglong2*>(hp + KC * BATCH + k * BATCH);
                float4 uA = *reinterpret_cast<const float4*>(up + k * NC);
                float4 uB = *reinterpret_cast<const float4*>(up + k * NC + 4);
                ull s0 = pack2(uA.x), s1 = pack2(uA.y), s2 = pack2(uA.z), s3 = pack2(uA.w);
                ull s4 = pack2(uB.x), s5 = pack2(uB.y), s6 = pack2(uB.z), s7 = pack2(uB.w);
                fma2(acc[0][0][0], hA.x, s0); fma2(acc[0][1][0], hA.y, s0);
                fma2(acc[0][0][1], hA.x, s1); fma2(acc[0][1][1], hA.y, s1);
                fma2(acc[0][0][2], hA.x, s2); fma2(acc[0][1][2], hA.y, s2);
                fma2(acc[0][0][3], hA.x, s3); fma2(acc[0][1][3], hA.y, s3);
                fma2(acc[0][0][4], hA.x, s4); fma2(acc[0][1][4], hA.y, s4);
                fma2(acc[0][0][5], hA.x, s5); fma2(acc[0][1][5], hA.y, s5);
                fma2(acc[0][0][6], hA.x, s6); fma2(acc[0][1][6], hA.y, s6);
                fma2(acc[0][0][7], hA.x, s7); fma2(acc[0][1][7], hA.y, s7);
                fma2(acc[1][0][0], hB.x, s0); fma2(acc[1][1][0], hB.y, s0);
                fma2(acc[1][0][1], hB.x, s1); fma2(acc[1][1][1], hB.y, s1);
                fma2(acc[1][0][2], hB.x, s2); fma2(acc[1][1][2], hB.y, s2);
                fma2(acc[1][0][3], hB.x, s3); fma2(acc[1][1][3], hB.y, s3);
                fma2(acc[1][0][4], hB.x, s4); fma2(acc[1][1][4], hB.y, s4);
                fma2(acc[1][0][5], hB.x, s5); fma2(acc[1][1][5], hB.y, s5);
                fma2(acc[1][0][6], hB.x, s6); fma2(acc[1][1][6], hB.y, s6);
                fma2(acc[1][0][7], hB.x, s7); fma2(acc[1][1][7], hB.y, s7);
            }
        }

        // ---- publish partials (plain stcg; the values are the ready flags) ----
        #pragma unroll
        for (int d = 0; d < 2; d++)
            #pragma unroll
            for (int i = 0; i < 8; i++) {
                float2 a0 = unpack2(acc[d][0][i]);
                float2 a1 = unpack2(acc[d][1][i]);
                __stcg(reinterpret_cast<float4*>(
                           &g_part[pb][d][kc][c0 + cc + i][b0]),
                       make_float4(a0.x, a0.y, a1.x, a1.y));
            }

        // ---- prefetch x for the reduce ----
        int xt = rdir ? (T_STEPS - 1 - t) : t;
        float4 xv = __ldcg(reinterpret_cast<const float4*>(
                        g_xw + (xt * UNITS + ru) * BATCH) + rb4);

        // all GEMM reads of h_s done before staging overwrites it later
        __syncthreads();

        // ---- poll the 16 partials of our slice ----
        float4* pslot[CK];
        float4  pv[CK];
        #pragma unroll
        for (int j = 0; j < CK; j++) {
            pslot[j] = reinterpret_cast<float4*>(&g_part[pb][rdir][j][ru][0]) + rb4;
            pv[j] = ld_poll(pslot[j]);
        }
        for (;;) {
            unsigned bad = 0;
            #pragma unroll
            for (int j = 0; j < CK; j++)
                if (nan4(pv[j])) { bad = 1; pv[j] = ld_poll(pslot[j]); }
            if (!bad) break;
        }
        // reset slots to NaN for round t+3
        #pragma unroll
        for (int j = 0; j < CK; j++) __stcg(pslot[j], qn4);
        fence_argp();   // acquire(polls) + release(resets before replica stores)

        // ---- reduce + x + relu + clip ----
        {
            float4 s = xv;
            #pragma unroll
            for (int j = 0; j < CK; j++) {
                s.x += pv[j].x; s.y += pv[j].y; s.z += pv[j].z; s.w += pv[j].w;
            }
            hn.x = fminf(fmaxf(s.x, 0.f), CLIPV);
            hn.y = fminf(fmaxf(s.y, 0.f), CLIPV);
            hn.z = fminf(fmaxf(s.z, 0.f), CLIPV);
            hn.w = fminf(fmaxf(s.w, 0.f), CLIPV);
        }
        // ---- publish slice to all 8 consumers' private replicas ----
        #pragma unroll
        for (int c = 0; c < CN; c++)
            __stcg(reinterpret_cast<float4*>(
                       &g_hrep[pb][kc][c][rdir][nc * 8 + lu][0]) + rb4, hn);

        // ---- stage h_t from own replica (poll = stage), except last round ----
        if (t < T_STEPS - 1) {
            float4* hbase = reinterpret_cast<float4*>(&g_hrep[pb][kc][nc][0][0][0]);
            float4* hslot[8];
            float4  hv[8];
            #pragma unroll
            for (int i = 0; i < 8; i++) {
                hslot[i] = hbase + tid * 8 + i;
                hv[i] = ld_poll(hslot[i]);
            }
            for (;;) {
                unsigned bad = 0;
                #pragma unroll
                for (int i = 0; i < 8; i++)
                    if (nan4(hv[i])) { bad = 1; hv[i] = ld_poll(hslot[i]); }
                if (!bad) break;
            }
            #pragma unroll
            for (int i = 0; i < 8; i++)
                reinterpret_cast<float4*>(h_s)[tid * 8 + i] = hv[i];
            // reset replica for round t+3
            #pragma unroll
            for (int i = 0; i < 8; i++) __stcg(hslot[i], qn4);
            fence_argp();   // acquire(h polls) + release(resets before partials t+1)
            __syncthreads();
        }

        pb = pb + 1; if (pb == 3) pb = 0;
    }

    // ---- epilogue: combine dirs of the final slice, write out ----
    __syncthreads();                       // U_s free; reuse as scratch
    float4* fin = reinterpret_cast<float4*>(U_s);
    fin[tid] = hn;                         // [rdir*64 + lu*8 + rb4]
    __syncthreads();
    if (rdir == 0) {
        float4 f0 = fin[tid];
        float4 f1 = fin[64 + tid];
        float4 s = make_float4(f0.x + f1.x, f0.y + f1.y, f0.z + f1.z, f0.w + f1.w);
        int b = rb4 * 4;
        out[(b + 0) * UNITS + ru] = s.x;
        out[(b + 1) * UNITS + ru] = s.y;
        out[(b + 2) * UNITS + ru] = s.z;
        out[(b + 3) * UNITS + ru] = s.w;
    }
}

// ---------------------------------------------------------------------------
extern "C" void kernel_launch(void* const* d_in, const int* in_sizes, int n_in,
                              void* d_out, int out_size) {
    const float* inp  = (const float*)d_in[0];  // [32, 800, 161]
    const float* W    = (const float*)d_in[1];  // [161, 1024]
    const float* Uw   = (const float*)d_in[2];  // [1024, 1024]
    const float* bias = (const float*)d_in[3];  // [1024]
    float* out        = (float*)d_out;          // [32, 1024]

    cudaFuncSetAttribute(rnn_kernel, cudaFuncAttributeMaxDynamicSharedMemorySize,
                         SMEM_BYTES);

    init_kernel<<<1024, TPB>>>();
    xw_kernel<<<dim3(8, T_STEPS, 1), TPB>>>(inp, W, bias);
    rnn_kernel<<<GRID, TPR, SMEM_BYTES>>>(Uw, out);
}